// round 9
// baseline (speedup 1.0000x reference)
#include <cuda_runtime.h>
#include <cuda_bf16.h>
#include <cstdint>

// Problem constants (fixed by setup_inputs): T=128, N=2048, D=256, w=3
#define T_SNAP 128
#define N_NODE 2048
#define D_HID  256
#define WIN    3
#define ROWS   (T_SNAP * N_NODE)   // 262144

// Scratch (allocation-free rule: __device__ globals)
__device__ float g_score[ROWS];
__device__ float g_p[ROWS];
// Pre-packed W: g_Wb[(c*16 + k2)*256 + n] = bf16x2{ W[32c+2k2][n], W[32c+2k2+1][n] }
__device__ uint32_t g_Wb[8 * 16 * 256];   // 128 KB

// ---------------------------------------------------------------------------
__device__ __forceinline__ uint32_t pack_bf16(float lo, float hi) {
    __nv_bfloat162 h = __floats2bfloat162_rn(lo, hi);
    return *reinterpret_cast<uint32_t*>(&h);
}

__device__ __forceinline__ void mma_bf16(float* c, const uint32_t* a, const uint32_t* b) {
    asm volatile(
        "mma.sync.aligned.m16n8k16.row.col.f32.bf16.bf16.f32 "
        "{%0,%1,%2,%3}, {%4,%5,%6,%7}, {%8,%9}, {%0,%1,%2,%3};"
        : "+f"(c[0]), "+f"(c[1]), "+f"(c[2]), "+f"(c[3])
        : "r"(a[0]), "r"(a[1]), "r"(a[2]), "r"(a[3]), "r"(b[0]), "r"(b[1]));
}

__device__ __forceinline__ void cp_async16(uint32_t smem_dst, const void* gptr) {
    asm volatile("cp.async.cg.shared.global [%0], [%1], 16;"
                 :: "r"(smem_dst), "l"(gptr) : "memory");
}
__device__ __forceinline__ void cp_commit() {
    asm volatile("cp.async.commit_group;" ::: "memory");
}
__device__ __forceinline__ void cp_wait_all() {
    asm volatile("cp.async.wait_group 0;" ::: "memory");
}

// ---------------------------------------------------------------------------
// Kernel 0: pack W into bf16x2 chunk layout (one-shot, ~µs)
// ---------------------------------------------------------------------------
__global__ __launch_bounds__(256) void prep_w_kernel(const float* __restrict__ W)
{
    int idx = blockIdx.x * 256 + threadIdx.x;  // 0..32767
    int n  = idx & 255;
    int kk = idx >> 8;                         // global k-pair 0..127
    g_Wb[idx] = pack_bf16(W[(2 * kk) * D_HID + n], W[(2 * kk + 1) * D_HID + n]);
}

// ---------------------------------------------------------------------------
// Kernel 1 (mma.sync bf16, M=32 for 3-CTA/SM occupancy):
//   score[row] = proj . tanh( X[row,:] @ W )
// 8192 CTAs; per CTA M=32 rows x N=256, BK=32 x 8 chunks. Each X row read by
// exactly ONE CTA (no duplicated A traffic). 8 warps each own all 32 rows x
// 32 cols (mt=2, nt=4). Double-buffered smem; B via cp.async from g_Wb
// (L2-hot); A LDG->pack->STS overlapped. acc=32 regs -> 3 CTAs/SM.
// ---------------------------------------------------------------------------
#define AS_STRIDE 20    // u32: banks (20*qid+qlane)%32 all distinct
#define BS_STRIDE 264   // u32: banks (8*qlane+qid)%32 all distinct

__global__ __launch_bounds__(256, 3) void score_kernel(
    const float4* __restrict__ X4,
    const float*  __restrict__ proj)
{
    __shared__ uint32_t As[2][32 * AS_STRIDE];   // 5 KB
    __shared__ uint32_t Bs[2][16 * BS_STRIDE];   // 33.8 KB
    __shared__ float sproj[D_HID];
    __shared__ float part[8][32];

    const int tid    = threadIdx.x;
    const int lane   = tid & 31;
    const int wid    = tid >> 5;                 // warp_n 0..7
    const int qid    = lane >> 2;                // 0..7
    const int qlane  = lane & 3;                 // 0..3
    const int row0   = blockIdx.x * 32;

    sproj[tid] = proj[tid];

    // A staging coords: 256 float4 segments, 1 per thread
    const int am = tid >> 3, ac = tid & 7;
    const uint32_t bs_base = (uint32_t)__cvta_generic_to_shared(&Bs[0][0]);

    float acc[2][4][4];
    #pragma unroll
    for (int mt = 0; mt < 2; mt++)
        #pragma unroll
        for (int nt = 0; nt < 4; nt++)
            #pragma unroll
            for (int i = 0; i < 4; i++) acc[mt][nt][i] = 0.0f;

    auto stageB = [&](int c, int bf) {
        #pragma unroll
        for (int i = 0; i < 4; i++) {
            int seg = tid + i * 256;             // 0..1023
            int k2  = seg >> 6;
            int ng  = seg & 63;
            cp_async16(bs_base + (bf * 16 * BS_STRIDE + k2 * BS_STRIDE + ng * 4) * 4,
                       &g_Wb[(c * 16 + k2) * 256 + ng * 4]);
        }
    };
    auto stsA = [&](int bf, float4 v) {
        uint2 u;
        u.x = pack_bf16(v.x, v.y); u.y = pack_bf16(v.z, v.w);
        *reinterpret_cast<uint2*>(&As[bf][am * AS_STRIDE + ac * 2]) = u;
    };

    // ---- Prologue: stage chunk 0 ----
    float4 pa = X4[(row0 + am) * 64 + ac];
    stageB(0, 0); cp_commit();
    stsA(0, pa);
    cp_wait_all();
    __syncthreads();

    #pragma unroll 1
    for (int c = 0; c < 8; ++c) {
        const int buf = c & 1;
        const int nxt = buf ^ 1;

        if (c < 7) {
            stageB(c + 1, nxt); cp_commit();
            pa = X4[(row0 + am) * 64 + (c + 1) * 8 + ac];
        }

        #pragma unroll
        for (int ks = 0; ks < 2; ks++) {
            const int k2b = ks * 8;
            uint32_t a[2][4];
            #pragma unroll
            for (int mt = 0; mt < 2; mt++) {
                int r = mt * 16 + qid;
                a[mt][0] = As[buf][r * AS_STRIDE + k2b + qlane];
                a[mt][1] = As[buf][(r + 8) * AS_STRIDE + k2b + qlane];
                a[mt][2] = As[buf][r * AS_STRIDE + k2b + qlane + 4];
                a[mt][3] = As[buf][(r + 8) * AS_STRIDE + k2b + qlane + 4];
            }
            uint32_t b[4][2];
            #pragma unroll
            for (int nt = 0; nt < 4; nt++) {
                int n = wid * 32 + nt * 8 + qid;
                b[nt][0] = Bs[buf][(k2b + qlane)     * BS_STRIDE + n];
                b[nt][1] = Bs[buf][(k2b + qlane + 4) * BS_STRIDE + n];
            }
            #pragma unroll
            for (int mt = 0; mt < 2; mt++)
                #pragma unroll
                for (int nt = 0; nt < 4; nt++)
                    mma_bf16(acc[mt][nt], a[mt], b[nt]);
        }

        if (c < 7) {
            stsA(nxt, pa);
            cp_wait_all();
            __syncthreads();
        }
    }

    // Fused epilogue: per-row sum of tanh(u)*proj over this warp's 32 cols.
    float psum[2][2];
    psum[0][0] = psum[0][1] = psum[1][0] = psum[1][1] = 0.0f;
    #pragma unroll
    for (int mt = 0; mt < 2; mt++)
        #pragma unroll
        for (int nt = 0; nt < 4; nt++) {
            int cb = wid * 32 + nt * 8 + 2 * qlane;
            float p0 = sproj[cb], p1 = sproj[cb + 1];
            psum[mt][0] += tanhf(acc[mt][nt][0]) * p0 + tanhf(acc[mt][nt][1]) * p1;
            psum[mt][1] += tanhf(acc[mt][nt][2]) * p0 + tanhf(acc[mt][nt][3]) * p1;
        }
    #pragma unroll
    for (int off = 1; off < 4; off <<= 1) {
        #pragma unroll
        for (int mt = 0; mt < 2; mt++) {
            psum[mt][0] += __shfl_xor_sync(0xffffffffu, psum[mt][0], off);
            psum[mt][1] += __shfl_xor_sync(0xffffffffu, psum[mt][1], off);
        }
    }
    __syncthreads();
    if (qlane == 0) {
        #pragma unroll
        for (int mt = 0; mt < 2; mt++) {
            part[wid][mt * 16 + qid]     = psum[mt][0];
            part[wid][mt * 16 + qid + 8] = psum[mt][1];
        }
    }
    __syncthreads();
    if (tid < 32) {
        float s = 0.0f;
        #pragma unroll
        for (int wq = 0; wq < 8; wq++) s += part[wq][tid];
        g_score[row0 + tid] = s;
    }
}

// ---------------------------------------------------------------------------
// Kernel 2: p[j,:] = softmax over N of score[j,:]   (one block per row j)
// ---------------------------------------------------------------------------
__global__ __launch_bounds__(256) void softmax_kernel()
{
    __shared__ float red_max[8];
    __shared__ float red_sum[8];
    const int j   = blockIdx.x;
    const int tid = threadIdx.x;
    const float* row = g_score + j * N_NODE;

    float v[8];
    float m = -1e30f;
    #pragma unroll
    for (int i = 0; i < 8; i++) {
        v[i] = row[tid + i * 256];
        m = fmaxf(m, v[i]);
    }
    #pragma unroll
    for (int off = 16; off > 0; off >>= 1)
        m = fmaxf(m, __shfl_xor_sync(0xffffffffu, m, off));
    if ((tid & 31) == 0) red_max[tid >> 5] = m;
    __syncthreads();
    float bm = red_max[0];
    #pragma unroll
    for (int wq = 1; wq < 8; wq++) bm = fmaxf(bm, red_max[wq]);

    float s = 0.0f;
    #pragma unroll
    for (int i = 0; i < 8; i++) {
        v[i] = expf(v[i] - bm);
        s += v[i];
    }
    #pragma unroll
    for (int off = 16; off > 0; off >>= 1)
        s += __shfl_xor_sync(0xffffffffu, s, off);
    if ((tid & 31) == 0) red_sum[tid >> 5] = s;
    __syncthreads();
    float bs = 0.0f;
    #pragma unroll
    for (int wq = 0; wq < 8; wq++) bs += red_sum[wq];
    float inv = 1.0f / bs;

    #pragma unroll
    for (int i = 0; i < 8; i++)
        g_p[j * N_NODE + tid + i * 256] = v[i] * inv;
}

// ---------------------------------------------------------------------------
// Kernel 3: out. Snapshot-aligned blocks (uniform branch); 4 float4/thread
// at fixed (i,n) -> p loads amortized, 12 LDGs in flight.
// ---------------------------------------------------------------------------
__global__ __launch_bounds__(256) void out_kernel(
    const float4* __restrict__ X4,
    float4* __restrict__ out4)
{
    const int STRIDE_T = N_NODE * 64;           // float4 per snapshot
    const int i  = blockIdx.x >> 7;             // snapshot 0..127
    const int n  = ((blockIdx.x & 127) << 4) + (threadIdx.x >> 4);
    const int dp = threadIdx.x & 15;
    const int base = (i * N_NODE + n) * 64;

    if (i < WIN) {
        #pragma unroll
        for (int q = 0; q < 4; q++)
            out4[base + dp + q * 16] = X4[base + dp + q * 16];
    } else {
        const int pb = (i - 3) * N_NODE + n;
        const float p0 = g_p[pb];
        const float p1 = g_p[pb + N_NODE];
        const float p2 = g_p[pb + 2 * N_NODE];
        #pragma unroll
        for (int q = 0; q < 4; q++) {
            int d = base + dp + q * 16;
            float4 a = X4[d - 3 * STRIDE_T];
            float4 b = X4[d - 2 * STRIDE_T];
            float4 c = X4[d - 1 * STRIDE_T];
            float4 o;
            o.x = p0 * a.x + p1 * b.x + p2 * c.x;
            o.y = p0 * a.y + p1 * b.y + p2 * c.y;
            o.z = p0 * a.z + p1 * b.z + p2 * c.z;
            o.w = p0 * a.w + p1 * b.w + p2 * c.w;
            out4[d] = o;
        }
    }
}

// ---------------------------------------------------------------------------
extern "C" void kernel_launch(void* const* d_in, const int* in_sizes, int n_in,
                              void* d_out, int out_size)
{
    const float* X    = (const float*)d_in[0];  // (128, 2048, 256)
    const float* W    = (const float*)d_in[1];  // (256, 256)
    const float* proj = (const float*)d_in[2];  // (256, 1)
    float* out        = (float*)d_out;

    prep_w_kernel<<<128, 256>>>(W);
    score_kernel<<<ROWS / 32, 256>>>((const float4*)X, proj);
    softmax_kernel<<<T_SNAP, 256>>>();
    out_kernel<<<T_SNAP * 128, 256>>>((const float4*)X, (float4*)out);
}

// round 10
// speedup vs baseline: 1.1458x; 1.1458x over previous
#include <cuda_runtime.h>
#include <cuda_bf16.h>
#include <cstdint>

// Problem constants (fixed by setup_inputs): T=128, N=2048, D=256, w=3
#define T_SNAP 128
#define N_NODE 2048
#define D_HID  256
#define WIN    3
#define ROWS   (T_SNAP * N_NODE)   // 262144

// Scratch (allocation-free rule: __device__ globals)
__device__ float g_score[ROWS];
__device__ float g_p[ROWS];
// Pre-packed W: g_Wb[(c*16 + k2)*256 + n] = bf16x2{ W[32c+2k2][n], W[32c+2k2+1][n] }
__device__ uint32_t g_Wb[8 * 16 * 256];   // 128 KB

// ---------------------------------------------------------------------------
__device__ __forceinline__ uint32_t pack_bf16(float lo, float hi) {
    __nv_bfloat162 h = __floats2bfloat162_rn(lo, hi);
    return *reinterpret_cast<uint32_t*>(&h);
}

__device__ __forceinline__ void mma_bf16(float* c, const uint32_t* a, const uint32_t* b) {
    asm volatile(
        "mma.sync.aligned.m16n8k16.row.col.f32.bf16.bf16.f32 "
        "{%0,%1,%2,%3}, {%4,%5,%6,%7}, {%8,%9}, {%0,%1,%2,%3};"
        : "+f"(c[0]), "+f"(c[1]), "+f"(c[2]), "+f"(c[3])
        : "r"(a[0]), "r"(a[1]), "r"(a[2]), "r"(a[3]), "r"(b[0]), "r"(b[1]));
}

__device__ __forceinline__ void cp_async16(uint32_t smem_dst, const void* gptr) {
    asm volatile("cp.async.cg.shared.global [%0], [%1], 16;"
                 :: "r"(smem_dst), "l"(gptr) : "memory");
}
__device__ __forceinline__ void cp_commit() {
    asm volatile("cp.async.commit_group;" ::: "memory");
}
__device__ __forceinline__ void cp_wait_all() {
    asm volatile("cp.async.wait_group 0;" ::: "memory");
}

// ---------------------------------------------------------------------------
// Kernel 0: pack W into bf16x2 chunk layout (one-shot, ~µs)
// ---------------------------------------------------------------------------
__global__ __launch_bounds__(256) void prep_w_kernel(const float* __restrict__ W)
{
    int idx = blockIdx.x * 256 + threadIdx.x;  // 0..32767
    int n  = idx & 255;
    int kk = idx >> 8;                         // global k-pair 0..127
    g_Wb[idx] = pack_bf16(W[(2 * kk) * D_HID + n], W[(2 * kk + 1) * D_HID + n]);
}

// ---------------------------------------------------------------------------
// Kernel 1 (mma.sync bf16, pipelined — best measured config):
//   score[row] = proj . tanh( X[row,:] @ W )
// Block: 256 threads = 8 warps, 2(M) x 4(N). Tile M=64, N=256, BK=32 x 8.
// Double-buffered smem; B via cp.async from pre-packed g_Wb (L2-hot); A is
// LDG-prefetched into regs, converted, STS'd while MMAs run on the other buf.
// ---------------------------------------------------------------------------
#define AS_STRIDE 20    // u32: banks (20*qid+qlane)%32 all distinct
#define BS_STRIDE 264   // u32: banks (8*qlane+qid)%32 all distinct

__global__ __launch_bounds__(256, 2) void score_kernel(
    const float4* __restrict__ X4,
    const float*  __restrict__ proj)
{
    __shared__ uint32_t As[2][64 * AS_STRIDE];   // 10 KB
    __shared__ uint32_t Bs[2][16 * BS_STRIDE];   // 33.8 KB
    __shared__ float sproj[D_HID];
    __shared__ float part[4][64];

    const int tid    = threadIdx.x;
    const int lane   = tid & 31;
    const int wid    = tid >> 5;
    const int warp_m = wid >> 2;
    const int warp_n = wid & 3;
    const int qid    = lane >> 2;
    const int qlane  = lane & 3;
    const int row0   = blockIdx.x * 64;

    sproj[tid] = proj[tid];

    // Per-thread fixed load coordinates
    const int am0 = tid >> 3,         ac0 = tid & 7;
    const int am1 = (tid + 256) >> 3, ac1 = (tid + 256) & 7;
    const uint32_t bs_base = (uint32_t)__cvta_generic_to_shared(&Bs[0][0]);

    float acc[2][8][4];
    #pragma unroll
    for (int mt = 0; mt < 2; mt++)
        #pragma unroll
        for (int nt = 0; nt < 8; nt++)
            #pragma unroll
            for (int i = 0; i < 4; i++) acc[mt][nt][i] = 0.0f;

    auto stageB = [&](int c, int bf) {
        #pragma unroll
        for (int i = 0; i < 4; i++) {
            int seg = tid + i * 256;             // 0..1023
            int k2  = seg >> 6;
            int ng  = seg & 63;
            cp_async16(bs_base + (bf * 16 * BS_STRIDE + k2 * BS_STRIDE + ng * 4) * 4,
                       &g_Wb[(c * 16 + k2) * 256 + ng * 4]);
        }
    };
    auto stsA = [&](int bf, float4 v0, float4 v1) {
        uint2 u;
        u.x = pack_bf16(v0.x, v0.y); u.y = pack_bf16(v0.z, v0.w);
        *reinterpret_cast<uint2*>(&As[bf][am0 * AS_STRIDE + ac0 * 2]) = u;
        u.x = pack_bf16(v1.x, v1.y); u.y = pack_bf16(v1.z, v1.w);
        *reinterpret_cast<uint2*>(&As[bf][am1 * AS_STRIDE + ac1 * 2]) = u;
    };

    // ---- Prologue: stage chunk 0 ----
    float4 pa0 = X4[(row0 + am0) * 64 + ac0];
    float4 pa1 = X4[(row0 + am1) * 64 + ac1];
    stageB(0, 0); cp_commit();
    stsA(0, pa0, pa1);
    cp_wait_all();
    __syncthreads();

    #pragma unroll 1
    for (int c = 0; c < 8; ++c) {
        const int buf = c & 1;
        const int nxt = buf ^ 1;

        // Stage chunk c+1: A LDG first (longest latency), then B cp.async
        if (c < 7) {
            pa0 = X4[(row0 + am0) * 64 + (c + 1) * 8 + ac0];
            pa1 = X4[(row0 + am1) * 64 + (c + 1) * 8 + ac1];
            stageB(c + 1, nxt); cp_commit();
        }

        // MMAs on current buffer
        #pragma unroll
        for (int ks = 0; ks < 2; ks++) {
            const int k2b = ks * 8;
            uint32_t a[2][4];
            #pragma unroll
            for (int mt = 0; mt < 2; mt++) {
                int r = warp_m * 32 + mt * 16 + qid;
                a[mt][0] = As[buf][r * AS_STRIDE + k2b + qlane];
                a[mt][1] = As[buf][(r + 8) * AS_STRIDE + k2b + qlane];
                a[mt][2] = As[buf][r * AS_STRIDE + k2b + qlane + 4];
                a[mt][3] = As[buf][(r + 8) * AS_STRIDE + k2b + qlane + 4];
            }
            uint32_t b[8][2];
            #pragma unroll
            for (int nt = 0; nt < 8; nt++) {
                int n = warp_n * 64 + nt * 8 + qid;
                b[nt][0] = Bs[buf][(k2b + qlane)     * BS_STRIDE + n];
                b[nt][1] = Bs[buf][(k2b + qlane + 4) * BS_STRIDE + n];
            }
            #pragma unroll
            for (int mt = 0; mt < 2; mt++)
                #pragma unroll
                for (int nt = 0; nt < 8; nt++)
                    mma_bf16(acc[mt][nt], a[mt], b[nt]);
        }

        if (c < 7) {
            stsA(nxt, pa0, pa1);
            cp_wait_all();
            __syncthreads();
        }
    }

    // Fused epilogue: per-row sum of tanh(u)*proj over this warp's 64 cols.
    float psum[2][2];
    psum[0][0] = psum[0][1] = psum[1][0] = psum[1][1] = 0.0f;
    #pragma unroll
    for (int mt = 0; mt < 2; mt++)
        #pragma unroll
        for (int nt = 0; nt < 8; nt++) {
            int cb = warp_n * 64 + nt * 8 + 2 * qlane;
            float p0 = sproj[cb], p1 = sproj[cb + 1];
            psum[mt][0] += tanhf(acc[mt][nt][0]) * p0 + tanhf(acc[mt][nt][1]) * p1;
            psum[mt][1] += tanhf(acc[mt][nt][2]) * p0 + tanhf(acc[mt][nt][3]) * p1;
        }
    #pragma unroll
    for (int off = 1; off < 4; off <<= 1) {
        #pragma unroll
        for (int mt = 0; mt < 2; mt++) {
            psum[mt][0] += __shfl_xor_sync(0xffffffffu, psum[mt][0], off);
            psum[mt][1] += __shfl_xor_sync(0xffffffffu, psum[mt][1], off);
        }
    }
    __syncthreads();
    if (qlane == 0) {
        #pragma unroll
        for (int mt = 0; mt < 2; mt++) {
            part[warp_n][warp_m * 32 + mt * 16 + qid]     = psum[mt][0];
            part[warp_n][warp_m * 32 + mt * 16 + qid + 8] = psum[mt][1];
        }
    }
    __syncthreads();
    if (tid < 64)
        g_score[row0 + tid] =
            part[0][tid] + part[1][tid] + part[2][tid] + part[3][tid];
}

// ---------------------------------------------------------------------------
// Kernel 2: p[j,:] = softmax over N of score[j,:]   (one block per row j)
// ---------------------------------------------------------------------------
__global__ __launch_bounds__(256) void softmax_kernel()
{
    __shared__ float red_max[8];
    __shared__ float red_sum[8];
    const int j   = blockIdx.x;
    const int tid = threadIdx.x;
    const float* row = g_score + j * N_NODE;

    float v[8];
    float m = -1e30f;
    #pragma unroll
    for (int i = 0; i < 8; i++) {
        v[i] = row[tid + i * 256];
        m = fmaxf(m, v[i]);
    }
    #pragma unroll
    for (int off = 16; off > 0; off >>= 1)
        m = fmaxf(m, __shfl_xor_sync(0xffffffffu, m, off));
    if ((tid & 31) == 0) red_max[tid >> 5] = m;
    __syncthreads();
    float bm = red_max[0];
    #pragma unroll
    for (int wq = 1; wq < 8; wq++) bm = fmaxf(bm, red_max[wq]);

    float s = 0.0f;
    #pragma unroll
    for (int i = 0; i < 8; i++) {
        v[i] = expf(v[i] - bm);
        s += v[i];
    }
    #pragma unroll
    for (int off = 16; off > 0; off >>= 1)
        s += __shfl_xor_sync(0xffffffffu, s, off);
    if ((tid & 31) == 0) red_sum[tid >> 5] = s;
    __syncthreads();
    float bs = 0.0f;
    #pragma unroll
    for (int wq = 0; wq < 8; wq++) bs += red_sum[wq];
    float inv = 1.0f / bs;

    #pragma unroll
    for (int i = 0; i < 8; i++)
        g_p[j * N_NODE + tid + i * 256] = v[i] * inv;
}

// ---------------------------------------------------------------------------
// Kernel 3: out. Snapshot-aligned blocks (uniform branch); 4 float4/thread
// at fixed (i,n) -> p loads amortized, 12 LDGs in flight.  (best: 79.4 µs)
// ---------------------------------------------------------------------------
__global__ __launch_bounds__(256) void out_kernel(
    const float4* __restrict__ X4,
    float4* __restrict__ out4)
{
    const int STRIDE_T = N_NODE * 64;           // float4 per snapshot
    const int i  = blockIdx.x >> 7;             // snapshot 0..127
    const int n  = ((blockIdx.x & 127) << 4) + (threadIdx.x >> 4);
    const int dp = threadIdx.x & 15;
    const int base = (i * N_NODE + n) * 64;

    if (i < WIN) {
        #pragma unroll
        for (int q = 0; q < 4; q++)
            out4[base + dp + q * 16] = X4[base + dp + q * 16];
    } else {
        const int pb = (i - 3) * N_NODE + n;
        const float p0 = g_p[pb];
        const float p1 = g_p[pb + N_NODE];
        const float p2 = g_p[pb + 2 * N_NODE];
        #pragma unroll
        for (int q = 0; q < 4; q++) {
            int d = base + dp + q * 16;
            float4 a = X4[d - 3 * STRIDE_T];
            float4 b = X4[d - 2 * STRIDE_T];
            float4 c = X4[d - 1 * STRIDE_T];
            float4 o;
            o.x = p0 * a.x + p1 * b.x + p2 * c.x;
            o.y = p0 * a.y + p1 * b.y + p2 * c.y;
            o.z = p0 * a.z + p1 * b.z + p2 * c.z;
            o.w = p0 * a.w + p1 * b.w + p2 * c.w;
            out4[d] = o;
        }
    }
}

// ---------------------------------------------------------------------------
extern "C" void kernel_launch(void* const* d_in, const int* in_sizes, int n_in,
                              void* d_out, int out_size)
{
    const float* X    = (const float*)d_in[0];  // (128, 2048, 256)
    const float* W    = (const float*)d_in[1];  // (256, 256)
    const float* proj = (const float*)d_in[2];  // (256, 1)
    float* out        = (float*)d_out;

    prep_w_kernel<<<128, 256>>>(W);
    score_kernel<<<ROWS / 64, 256>>>((const float4*)X, proj);
    softmax_kernel<<<T_SNAP, 256>>>();
    out_kernel<<<T_SNAP * 128, 256>>>((const float4*)X, (float4*)out);
}